// round 1
// baseline (speedup 1.0000x reference)
#include <cuda_runtime.h>
#include <math.h>

#define MAXN 1024

// ---------------- persistent device state (static, no runtime alloc) ----------------
__device__ float  g_S[MAXN * MAXN];      // symmetric distance matrix, MAXD on diag/dead
__device__ double g_cross[MAXN * MAXN];  // cross[a][b] = sum of Wsym over leaves(a) x leaves(b)
__device__ float  g_values[MAXN];
__device__ int    g_indices[MAXN];
__device__ int    g_label[MAXN];
__device__ unsigned g_keymax;            // order-encoded max(X)
__device__ unsigned g_keyabs;            // order-encoded max(|X|)

// order-preserving float <-> unsigned encoding (for atomicMax)
__device__ __forceinline__ unsigned enc_f(float f) {
    unsigned u = __float_as_uint(f);
    return (u & 0x80000000u) ? ~u : (u | 0x80000000u);
}
__device__ __forceinline__ float dec_f(unsigned k) {
    unsigned u = (k & 0x80000000u) ? (k ^ 0x80000000u) : ~k;
    return __uint_as_float(u);
}

__global__ void k_reset() { g_keymax = 0u; g_keyabs = 0u; }

__global__ void k_reduce(const float* __restrict__ X, int n) {
    float m = -INFINITY, a = 0.0f;
    for (int i = blockIdx.x * blockDim.x + threadIdx.x; i < n; i += gridDim.x * blockDim.x) {
        float v = X[i];
        m = fmaxf(m, v);
        a = fmaxf(a, fabsf(v));
    }
#pragma unroll
    for (int o = 16; o; o >>= 1) {
        m = fmaxf(m, __shfl_down_sync(0xffffffffu, m, o));
        a = fmaxf(a, __shfl_down_sync(0xffffffffu, a, o));
    }
    __shared__ float sm[32], sa[32];
    int lane = threadIdx.x & 31, wid = threadIdx.x >> 5;
    if (lane == 0) { sm[wid] = m; sa[wid] = a; }
    __syncthreads();
    if (wid == 0) {
        int nw = (blockDim.x + 31) >> 5;
        m = (lane < nw) ? sm[lane] : -INFINITY;
        a = (lane < nw) ? sa[lane] : 0.0f;
#pragma unroll
        for (int o = 16; o; o >>= 1) {
            m = fmaxf(m, __shfl_down_sync(0xffffffffu, m, o));
            a = fmaxf(a, __shfl_down_sync(0xffffffffu, a, o));
        }
        if (lane == 0) {
            atomicMax(&g_keymax, enc_f(m));
            atomicMax(&g_keyabs, enc_f(a));
        }
    }
}

__global__ void k_initS(const float* __restrict__ X, int D) {
    float maxd = dec_f(g_keyabs) * 1000.0f;
    float msim = dec_f(g_keymax);
    int n = D * D;
    for (int idx = blockIdx.x * blockDim.x + threadIdx.x; idx < n; idx += gridDim.x * blockDim.x) {
        int i = idx / D;
        int j = idx - i * D;
        g_S[idx] = (i == j) ? maxd : (msim - X[idx]);
    }
}

__global__ void k_initCross(const float* __restrict__ W, int D) {
    int n = D * D;
    for (int idx = blockIdx.x * blockDim.x + threadIdx.x; idx < n; idx += gridDim.x * blockDim.x) {
        int i = idx / D;
        int j = idx - i * D;
        g_cross[idx] = (double)W[idx] + (double)W[j * D + i];
    }
}

// one block per row: values[r] = min_{j>r} S[r][j], indices = lowest argmin
__global__ void k_initVals(int D) {
    int r = blockIdx.x;
    float maxd = dec_f(g_keyabs) * 1000.0f;
    float bv = maxd;
    int bi = 0x7fffffff;
    for (int j = r + 1 + (int)threadIdx.x; j < D; j += blockDim.x) {
        float x = g_S[r * D + j];
        if (x < bv || (x == bv && j < bi)) { bv = x; bi = j; }
    }
#pragma unroll
    for (int o = 16; o; o >>= 1) {
        float ov = __shfl_down_sync(0xffffffffu, bv, o);
        int   oi = __shfl_down_sync(0xffffffffu, bi, o);
        if (ov < bv || (ov == bv && oi < bi)) { bv = ov; bi = oi; }
    }
    __shared__ float sv[8];
    __shared__ int   si[8];
    int lane = threadIdx.x & 31, wid = threadIdx.x >> 5;
    if (lane == 0) { sv[wid] = bv; si[wid] = bi; }
    __syncthreads();
    if (threadIdx.x == 0) {
        int nw = (blockDim.x + 31) >> 5;
        for (int k = 1; k < nw; ++k) {
            if (sv[k] < bv || (sv[k] == bv && si[k] < bi)) { bv = sv[k]; bi = si[k]; }
        }
        g_values[r] = bv;
        g_indices[r] = (bi == 0x7fffffff) ? 0 : bi;
    }
}

// ---------------- the sequential HAC loop: one persistent block ----------------
__global__ void __launch_bounds__(1024, 1) k_hac(int D) {
    const int tid = threadIdx.x;
    const int lane = tid & 31, wid = tid >> 5;
    const int nw = blockDim.x >> 5;

    __shared__ float  s_val[MAXN];
    __shared__ int    s_idx[MAXN];
    __shared__ float  s_newv[MAXN];
    __shared__ float  s_cs[MAXN];
    __shared__ double s_energy[MAXN];
    __shared__ double s_within[MAXN];
    __shared__ int    s_slot[MAXN];
    __shared__ int    s_label[MAXN];
    __shared__ int    s_list[MAXN];
    __shared__ float  s_rv[32];
    __shared__ int    s_ri[32];
    __shared__ int    sh_m1, sh_m2, sh_take, sh_nrec;
    __shared__ float  sh_cs1, sh_cs2, sh_ncs;

    const float MAXDV = dec_f(g_keyabs) * 1000.0f;

    s_val[tid]    = g_values[tid];
    s_idx[tid]    = g_indices[tid];
    s_cs[tid]     = 1.0f;
    s_energy[tid] = 0.0;
    s_within[tid] = 0.0;
    s_slot[tid]   = tid;
    s_label[tid]  = tid;
    if (tid == 0) sh_nrec = 0;
    __syncthreads();

    for (int step = 0; step < D - 1; ++step) {
        // ---- 1. global argmin over values (lowest-index tie-break) ----
        float v = s_val[tid];
        int   ix = tid;
#pragma unroll
        for (int o = 16; o; o >>= 1) {
            float ov = __shfl_down_sync(0xffffffffu, v, o);
            int   oi = __shfl_down_sync(0xffffffffu, ix, o);
            if (ov < v || (ov == v && oi < ix)) { v = ov; ix = oi; }
        }
        if (lane == 0) { s_rv[wid] = v; s_ri[wid] = ix; }
        __syncthreads();
        if (wid == 0) {
            v  = (lane < nw) ? s_rv[lane] : MAXDV;
            ix = (lane < nw) ? s_ri[lane] : 0x7fffffff;
#pragma unroll
            for (int o = 16; o; o >>= 1) {
                float ov = __shfl_down_sync(0xffffffffu, v, o);
                int   oi = __shfl_down_sync(0xffffffffu, ix, o);
                if (ov < v || (ov == v && oi < ix)) { v = ov; ix = oi; }
            }
            if (lane == 0) {
                int m1 = ix;
                int m2 = s_idx[m1];
                float cs1 = s_cs[m1], cs2 = s_cs[m2];
                double c12 = g_cross[(size_t)m1 * D + m2];
                double me = s_within[m1] + s_within[m2] + c12;
                double es = s_energy[m1] + s_energy[m2];
                int take = (me >= es) ? 1 : 0;
                s_energy[m1] = take ? me : es;
                s_within[m1] = me;
                float ncs = cs1 + cs2;
                s_cs[m1] = ncs;
                sh_m1 = m1; sh_m2 = m2; sh_take = take;
                sh_cs1 = cs1; sh_cs2 = cs2; sh_ncs = ncs;
            }
        }
        __syncthreads();
        const int m1 = sh_m1, m2 = sh_m2, take = sh_take;
        const float cs1 = sh_cs1, cs2 = sh_cs2, ncs = sh_ncs;

        // ---- 2. merged distances (reference MAXD-mask semantics) ----
        {
            float a = g_S[(size_t)m1 * D + tid];
            float b = g_S[(size_t)m2 * D + tid];
            float nv = (a == MAXDV || tid == m2)
                           ? MAXDV
                           : __fdiv_rn(__fadd_rn(__fmul_rn(a, cs1), __fmul_rn(b, cs2)), ncs);
            s_newv[tid] = nv;
        }
        __syncthreads();

        // ---- 3. commit S row/col m1, kill m2; cross row/col add; labels; values ----
        {
            float nv = s_newv[tid];
            g_S[(size_t)m1 * D + tid] = nv;
            g_S[(size_t)tid * D + m1] = nv;
            g_S[(size_t)m2 * D + tid] = MAXDV;
            g_S[(size_t)tid * D + m2] = MAXDV;

            if (tid != m2) {
                double cv = g_cross[(size_t)m2 * D + tid];
                g_cross[(size_t)m1 * D + tid] += cv;
                g_cross[(size_t)tid * D + m1] += cv;
            }

            if (s_slot[tid] == m2) s_slot[tid] = m1;
            if (take && s_slot[tid] == m1) s_label[tid] = D + step;

            if (tid == m2) {
                s_val[tid] = MAXDV;
            } else if (tid == m1) {
                int p = atomicAdd(&sh_nrec, 1);
                s_list[p] = tid;
            } else if (s_val[tid] != MAXDV) {
                int oi = s_idx[tid];
                if (oi == m1 || oi == m2) {
                    int p = atomicAdd(&sh_nrec, 1);
                    s_list[p] = tid;
                } else if (m1 > tid) {
                    float cand = s_newv[tid];
                    if (cand < s_val[tid] || (cand == s_val[tid] && m1 < oi)) {
                        s_val[tid] = cand;
                        s_idx[tid] = m1;
                    }
                }
            }
        }
        __syncthreads();

        // ---- 4. recompute row-mins for invalidated rows (one warp per row) ----
        int nrec = sh_nrec;
        for (int k = wid; k < nrec; k += nw) {
            int r = s_list[k];
            float bv = MAXDV;
            int bi = 0x7fffffff;
            if (r == m1) {
                for (int j = r + 1 + lane; j < D; j += 32) {
                    float x = s_newv[j];
                    if (x < bv || (x == bv && j < bi)) { bv = x; bi = j; }
                }
            } else {
                for (int j = r + 1 + lane; j < D; j += 32) {
                    float x = g_S[(size_t)r * D + j];
                    if (x < bv || (x == bv && j < bi)) { bv = x; bi = j; }
                }
            }
#pragma unroll
            for (int o = 16; o; o >>= 1) {
                float ov = __shfl_down_sync(0xffffffffu, bv, o);
                int   oi2 = __shfl_down_sync(0xffffffffu, bi, o);
                if (ov < bv || (ov == bv && oi2 < bi)) { bv = ov; bi = oi2; }
            }
            if (lane == 0) {
                s_val[r] = bv;
                s_idx[r] = (bi == 0x7fffffff) ? 0 : bi;
            }
        }
        __syncthreads();
        if (tid == 0) sh_nrec = 0;  // next atomicAdd is 3 syncs away; safe
    }

    g_label[tid] = s_label[tid];
}

// R[i][j] = 1 iff i==j or label[i]==label[j] (labels only collide via take-merges)
__global__ void k_out(float* __restrict__ out, int D) {
    int n = D * D;
    for (int idx = blockIdx.x * blockDim.x + threadIdx.x; idx < n; idx += gridDim.x * blockDim.x) {
        int i = idx / D;
        int j = idx - i * D;
        out[idx] = (i == j || __ldg(&g_label[i]) == __ldg(&g_label[j])) ? 1.0f : 0.0f;
    }
}

extern "C" void kernel_launch(void* const* d_in, const int* in_sizes, int n_in,
                              void* d_out, int out_size) {
    const float* X = (const float*)d_in[0];
    const float* W = (const float*)d_in[1];
    int n = in_sizes[0];
    int D = (int)(sqrt((double)n) + 0.5);
    if (D > MAXN || D < 32) return;

    k_reset<<<1, 1>>>();
    k_reduce<<<256, 256>>>(X, n);
    k_initS<<<2048, 256>>>(X, D);
    k_initCross<<<2048, 256>>>(W, D);
    k_initVals<<<D, 256>>>(D);
    k_hac<<<1, D>>>(D);
    k_out<<<2048, 256>>>((float*)d_out, D);
}